// round 15
// baseline (speedup 1.0000x reference)
#include <cuda_runtime.h>
#include <cuda_fp16.h>
#include <cstdint>

// Shapes (fixed by the problem)
#define CH    32
#define DD    36
#define HH    48
#define WW    48
#define HW    (HH*WW)          // 2304
#define DHW   (DD*HW)          // 82944
#define PP    9
#define P2    81
#define ND    (DD/PP)          // 4
#define NW    (HW/PP)          // 256
#define LL    (ND*NW)          // 1024
#define M2    162              // 2*P2
#define KE2   128              // padded K: [values(81) | 47 zeros], fp16

// ---------------- device scratch (no allocs allowed) ----------------
__device__ __align__(16) __half g_weff2h[96 * 104];   // Wefft fp16 [kout][j], pads 0
__device__ float g_ux[CH * P2 * LL];          // Ut[c][j][l] (K-major, fp32)
__device__ float g_uy[CH * P2 * LL];
__device__ __half g_pA[CH * LL * KE2];        // px rows fp16 [81 | 0-pad]
__device__ __half g_pB[CH * LL * KE2];

// ---------------- helpers ----------------
__device__ __forceinline__ uint32_t smem_u32(const void* p) {
    uint32_t a;
    asm("{ .reg .u64 t; cvta.to.shared.u64 t, %1; cvt.u32.u64 %0, t; }"
        : "=r"(a) : "l"(p));
    return a;
}
__device__ __forceinline__ void cpa16(uint32_t s, const void* g) {
    asm volatile("cp.async.cg.shared.global [%0], [%1], 16;" :: "r"(s), "l"(g));
}
__device__ __forceinline__ void ldmx4(uint32_t& r0, uint32_t& r1,
                                      uint32_t& r2, uint32_t& r3, uint32_t a) {
    asm volatile("ldmatrix.sync.aligned.m8n8.x4.shared.b16 {%0,%1,%2,%3}, [%4];"
                 : "=r"(r0), "=r"(r1), "=r"(r2), "=r"(r3) : "r"(a));
}
__device__ __forceinline__ void ldmx4t(uint32_t& r0, uint32_t& r1,
                                       uint32_t& r2, uint32_t& r3, uint32_t a) {
    asm volatile("ldmatrix.sync.aligned.m8n8.x4.trans.shared.b16 {%0,%1,%2,%3}, [%4];"
                 : "=r"(r0), "=r"(r1), "=r"(r2), "=r"(r3) : "r"(a));
}
__device__ __forceinline__ void mma16816(float* d, const uint32_t* a,
                                         uint32_t b0, uint32_t b1) {
    asm volatile(
        "mma.sync.aligned.m16n8k16.row.col.f32.f16.f16.f32 "
        "{%0,%1,%2,%3}, {%4,%5,%6,%7}, {%8,%9}, {%0,%1,%2,%3};"
        : "+f"(d[0]), "+f"(d[1]), "+f"(d[2]), "+f"(d[3])
        : "r"(a[0]), "r"(a[1]), "r"(a[2]), "r"(a[3]), "r"(b0), "r"(b1));
}

// ---------------- Kernel 0: Weff fp16  [kout 96][j 104], pads zero ----------
__global__ void weff_kernel(const float* __restrict__ W1,
                            const float* __restrict__ W2,
                            __half* __restrict__ We2) {
    __shared__ float w2row[M2];
    int k = blockIdx.x;     // 0..95
    int j = threadIdx.x;    // 0..103
    if (k < P2)
        for (int m = j; m < M2; m += 104) w2row[m] = W2[k * M2 + m];
    __syncthreads();
    float s = 0.f;
    if (k < P2 && j < P2) {
        #pragma unroll 6
        for (int m = 0; m < M2; m++) s += w2row[m] * W1[m * P2 + j];
    }
    We2[k * 104 + j] = __float2half_rn(s);
}

// ---------------- Kernel 1: conv + unfold via smem transpose --------------
#define CV_THREADS 288
#define CV_SMEM ((9216 + 9216 + 1024 + 32) * 4)    // 73984 B
__global__ __launch_bounds__(CV_THREADS)
void conv_unfold(const float* __restrict__ x, const float* __restrict__ y,
                 const float* __restrict__ Wi, const float* __restrict__ bi,
                 const float* __restrict__ Wf, const float* __restrict__ bf_,
                 float* __restrict__ ux, float* __restrict__ uy) {
    extern __shared__ float cs[];
    float* xs = cs;            // [32][288]
    float* us = cs + 9216;     // [32][288]
    float* ws = cs + 18432;    // [32][32]
    float* bs = cs + 19456;    // [32]

    int z = blockIdx.z;
    const float* src = z ? y : x;
    const float* Wc  = z ? Wf : Wi;
    const float* bc  = z ? bf_ : bi;
    float* U         = z ? uy : ux;

    int tid = threadIdx.x;
    int d   = blockIdx.x;              // 0..35
    int pwb = blockIdx.y;              // 0..7
    int pd = d / PP, kd = d - pd * PP;

    for (int i = tid; i < CH * CH; i += CV_THREADS) ws[i] = Wc[i];
    if (tid < CH) bs[tid] = bc[tid];

    {   // coalesced load: 32 ch x 288 floats
        const float4* x4 = (const float4*)src;
        float4* xs4 = (float4*)xs;
        int base = d * (HW / 4) + pwb * 72;
        #pragma unroll
        for (int it = 0; it < 8; it++) {
            int idx = it * CV_THREADS + tid;
            int i = idx / 72, q = idx - i * 72;
            xs4[idx] = x4[i * (DHW / 4) + base + q];
        }
    }
    __syncthreads();

    {   // conv: each thread owns one voxel
        int v = tid;
        float xv[CH];
        #pragma unroll
        for (int i = 0; i < CH; i++) xv[i] = xs[i * 288 + v];
        #pragma unroll 4
        for (int c = 0; c < CH; c++) {
            float s = bs[c];
            #pragma unroll
            for (int i = 0; i < CH; i++) s += ws[c * CH + i] * xv[i];
            us[c * 288 + v] = s;
        }
    }
    __syncthreads();

    {   // coalesced write-out: rows (c,kw) of 32 l-values (8 float4)
        int l0 = pd * NW + pwb * 32;
        #pragma unroll
        for (int it = 0; it < 8; it++) {
            int idx = it * CV_THREADS + tid;       // 0..2303
            int row = idx >> 3, q = idx & 7;       // row: c*9+kw
            int c = row / PP, kw = row - c * PP;
            int vb = q * 4 * PP + kw;
            float4 f = make_float4(us[c * 288 + vb],
                                   us[c * 288 + vb + 9],
                                   us[c * 288 + vb + 18],
                                   us[c * 288 + vb + 27]);
            float4* g4 = (float4*)(U + ((size_t)(c * P2 + kd * PP + kw)) * LL + l0);
            g4[q] = f;
        }
    }
}

// ---------------- Kernel 2: res_trans on tensor cores ----------------------
#define SU_STRIDE 272                         // bytes per sU row (17*16)
#define SW_STRIDE 208                         // bytes per sW row (13*16)
#define RT2_SMEM (96 * SU_STRIDE + 96 * SW_STRIDE)   // 46080 B
__global__ __launch_bounds__(256)
void res_trans_tc(const float* __restrict__ U0, const float* __restrict__ U1,
                  __half* __restrict__ P0, __half* __restrict__ P1) {
    extern __shared__ char smb[];
    uint32_t sU = smem_u32(smb);
    uint32_t sW = sU + 96 * SU_STRIDE;

    int z  = blockIdx.z;
    const float* U = z ? U1 : U0;
    __half* Pout = z ? P1 : P0;

    int c   = blockIdx.y;
    int mb  = blockIdx.x * 128;
    int tid = threadIdx.x;
    int wid = tid >> 5, lane = tid & 31;
    int wm = wid & 1, wn = wid >> 1;          // m-slab 48 (x2), n-slab 32 (x4)

    const float* Ub = U + (size_t)c * (P2 * LL) + mb;
    #pragma unroll
    for (int it = 0; it < 12; it++) {
        int idx = it * 256 + tid;            // 0..3071 = 96 rows x 32 chunks
        int j = idx >> 5, lc = idx & 31;
        uint2 v;
        if (j < P2) {
            float4 f = *(const float4*)(Ub + (size_t)j * LL + lc * 4);
            __half2 h0 = __floats2half2_rn(f.x, f.y);
            __half2 h1 = __floats2half2_rn(f.z, f.w);
            v.x = *(uint32_t*)&h0; v.y = *(uint32_t*)&h1;
        } else { v.x = 0u; v.y = 0u; }
        *(uint2*)(smb + (sU - smem_u32(smb)) + j * SU_STRIDE + lc * 8) = v;
    }
    {
        const char* gW = (const char*)g_weff2h;
        for (int idx = tid; idx < 96 * 13; idx += 256) {
            int row = idx / 13, ch = idx - row * 13;
            cpa16(sW + row * SW_STRIDE + ch * 16, gW + row * SW_STRIDE + ch * 16);
        }
        asm volatile("cp.async.commit_group;" ::: "memory");
        asm volatile("cp.async.wait_group 0;" ::: "memory");
    }
    __syncthreads();

    float acc[3][4][4];
    #pragma unroll
    for (int i = 0; i < 3; i++)
        #pragma unroll
        for (int j = 0; j < 4; j++)
            #pragma unroll
            for (int q = 0; q < 4; q++) acc[i][j][q] = 0.f;

    int tr = lane & 15, tc = lane >> 4;

    #pragma unroll
    for (int ks = 0; ks < 6; ks++) {
        int j0 = ks * 16;
        uint32_t afr[3][4];
        #pragma unroll
        for (int i = 0; i < 3; i++) {
            int m0 = wm * 48 + i * 16;
            ldmx4(afr[i][0], afr[i][1], afr[i][2], afr[i][3],
                  sW + (m0 + tr) * SW_STRIDE + j0 * 2 + tc * 16);
        }
        uint32_t b0[4], b1[4];
        #pragma unroll
        for (int jj = 0; jj < 2; jj++) {
            int n0 = wn * 32 + jj * 16;
            uint32_t r0, r1, r2, r3;
            ldmx4t(r0, r1, r2, r3,
                   sU + (j0 + tr) * SU_STRIDE + (n0 + tc * 8) * 2);
            b0[jj*2]   = r0; b1[jj*2]   = r1;
            b0[jj*2+1] = r2; b1[jj*2+1] = r3;
        }
        #pragma unroll
        for (int i = 0; i < 3; i++)
            #pragma unroll
            for (int j = 0; j < 4; j++)
                mma16816(acc[i][j], afr[i], b0[j], b1[j]);
    }
    __syncthreads();

    __half* st = (__half*)smb;
    int r0 = lane >> 2, c0 = (lane & 3) * 2;
    #pragma unroll
    for (int i = 0; i < 3; i++) {
        #pragma unroll
        for (int j = 0; j < 4; j++) {
            int m0 = wm * 48 + i * 16 + r0;
            int n0 = wn * 32 + j * 8 + c0;
            #pragma unroll
            for (int q = 0; q < 4; q++) {
                float v = acc[i][j][q];
                v = (v > 0.f) ? v : 0.2f * v;
                int mm = m0 + (q >> 1) * 8;
                int nn = n0 + (q & 1);
                st[nn * 104 + mm] = __float2half_rn(v);
            }
        }
    }
    __syncthreads();

    uint4* g4 = (uint4*)(Pout + ((size_t)(c * LL + mb)) * KE2);
    const char* stb = smb;
    uint4 zero4 = make_uint4(0, 0, 0, 0);
    #pragma unroll
    for (int it = 0; it < 8; it++) {
        int idx = it * 256 + tid;            // 0..2047
        int r = idx >> 4, q = idx & 15;
        uint4 v = (q < 12) ? *(const uint4*)(stb + r * SW_STRIDE + q * 16) : zero4;
        g4[r * 16 + q] = v;
    }
}

// ---------------- Kernel 3: att GEMM, fp16 K=128, 512 threads --------------
// CTA tile 128x128; 16 warps, warp tile 32x32 (2 m-tiles x 4 n-tiles).
// Whole K resident: A 32KB + B 32KB = 64 KB, one barrier, 2 CTAs/SM.
#define AT_SMEM 65536
__global__ __launch_bounds__(512, 2)
void att_mma(const __half* __restrict__ pA,
             const __half* __restrict__ pB,
             float* __restrict__ att) {
    extern __shared__ char smb[];
    uint32_t sA = smem_u32(smb);
    uint32_t sB = sA + 32768;

    int tid  = threadIdx.x;
    int wid  = tid >> 5;
    int lane = tid & 31;
    int wm   = wid & 3;        // 4 m-slabs (32 rows)
    int wn   = wid >> 2;       // 4 n-slabs (32 cols)

    int c  = blockIdx.z;
    int mb = blockIdx.y * 128;
    int nb = blockIdx.x * 128;
    const char* Ab = (const char*)(pA + ((size_t)(c * LL + mb)) * KE2);
    const char* Bb = (const char*)(pB + ((size_t)(c * LL + nb)) * KE2);

    // load both tiles: 128 rows x 256 B each, swizzle ch^(row&7)
    #pragma unroll
    for (int it = 0; it < 4; it++) {
        int idx = it * 512 + tid;          // 0..2047
        int row = idx >> 4, ch = idx & 15;
        int chs = ch ^ (row & 7);
        cpa16(sA + row * 256 + chs * 16, Ab + row * 256 + ch * 16);
        cpa16(sB + row * 256 + chs * 16, Bb + row * 256 + ch * 16);
    }
    asm volatile("cp.async.commit_group;" ::: "memory");

    float acc[2][4][4];
    #pragma unroll
    for (int i = 0; i < 2; i++)
        #pragma unroll
        for (int j = 0; j < 4; j++)
            #pragma unroll
            for (int q = 0; q < 4; q++) acc[i][j][q] = 0.f;

    int tr   = lane & 15;
    int tc   = lane >> 4;
    int xorv = tr & 7;

    asm volatile("cp.async.wait_group 0;" ::: "memory");
    __syncthreads();

    uint32_t aRow = sA + (wm * 32 + tr) * 256;
    uint32_t bRow = sB + (wn * 32 + tr) * 256;

    #pragma unroll
    for (int k = 0; k < 8; k++) {
        uint32_t chs = (uint32_t)(((2 * k + tc) ^ xorv) << 4);
        uint32_t afr[2][4];
        #pragma unroll
        for (int i = 0; i < 2; i++)
            ldmx4(afr[i][0], afr[i][1], afr[i][2], afr[i][3],
                  aRow + i * 4096 + chs);
        uint32_t b0[4], b1[4];
        #pragma unroll
        for (int j = 0; j < 2; j++) {
            uint32_t r0, r1, r2, r3;
            ldmx4(r0, r1, r2, r3, bRow + j * 4096 + chs);
            b0[j*2]   = r0; b1[j*2]   = r2;
            b0[j*2+1] = r1; b1[j*2+1] = r3;
        }
        #pragma unroll
        for (int i = 0; i < 2; i++)
            #pragma unroll
            for (int j = 0; j < 4; j++)
                mma16816(acc[i][j], afr[i], b0[j], b1[j]);
    }

    // epilogue
    const float scale = 1.0f / 81.0f;
    int r0 = lane >> 2;
    int c0 = (lane & 3) * 2;
    #pragma unroll
    for (int i = 0; i < 2; i++) {
        #pragma unroll
        for (int j = 0; j < 4; j++) {
            size_t row = (size_t)(mb + wm * 32 + i * 16 + r0);
            float* o = att + (size_t)c * LL * LL + row * LL
                     + nb + wn * 32 + j * 8 + c0;
            *(float2*)o            = make_float2(acc[i][j][0] * scale,
                                                 acc[i][j][1] * scale);
            *(float2*)(o + 8 * LL) = make_float2(acc[i][j][2] * scale,
                                                 acc[i][j][3] * scale);
        }
    }
}

// ---------------- launch ----------------
extern "C" void kernel_launch(void* const* d_in, const int* in_sizes, int n_in,
                              void* d_out, int out_size) {
    const float* x     = (const float*)d_in[0];
    const float* y     = (const float*)d_in[1];
    const float* W_img = (const float*)d_in[2];
    const float* b_img = (const float*)d_in[3];
    const float* W_fea = (const float*)d_in[4];
    const float* b_fea = (const float*)d_in[5];
    const float* W1    = (const float*)d_in[6];
    const float* W2    = (const float*)d_in[7];
    float* out = (float*)d_out;

    float *ux, *uy;
    __half *we2, *pA, *pB;
    cudaGetSymbolAddress((void**)&we2, g_weff2h);
    cudaGetSymbolAddress((void**)&ux,  g_ux);
    cudaGetSymbolAddress((void**)&uy,  g_uy);
    cudaGetSymbolAddress((void**)&pA,  g_pA);
    cudaGetSymbolAddress((void**)&pB,  g_pB);

    static bool attr_set = false;
    if (!attr_set) {
        cudaFuncSetAttribute(att_mma, cudaFuncAttributeMaxDynamicSharedMemorySize,
                             AT_SMEM);
        cudaFuncSetAttribute(res_trans_tc,
                             cudaFuncAttributeMaxDynamicSharedMemorySize, RT2_SMEM);
        cudaFuncSetAttribute(conv_unfold,
                             cudaFuncAttributeMaxDynamicSharedMemorySize, CV_SMEM);
        attr_set = true;
    }

    weff_kernel<<<96, 104>>>(W1, W2, we2);
    {
        dim3 g(DD, 8, 2);
        conv_unfold<<<g, CV_THREADS, CV_SMEM>>>(x, y, W_img, b_img,
                                                W_fea, b_fea, ux, uy);
    }
    {
        dim3 g(LL / 128, CH, 2);          // (8, 32, 2)
        res_trans_tc<<<g, 256, RT2_SMEM>>>(ux, uy, pA, pB);
    }
    {
        dim3 g(LL / 128, LL / 128, CH);   // (8, 8, 32)
        att_mma<<<g, 512, AT_SMEM>>>(pA, pB, out);
    }
}

// round 17
// speedup vs baseline: 1.0728x; 1.0728x over previous
#include <cuda_runtime.h>
#include <cuda_fp16.h>
#include <cstdint>

// Shapes (fixed by the problem)
#define CH    32
#define DD    36
#define HH    48
#define WW    48
#define HW    (HH*WW)          // 2304
#define DHW   (DD*HW)          // 82944
#define PP    9
#define P2    81
#define ND    (DD/PP)          // 4
#define NW    (HW/PP)          // 256
#define LL    (ND*NW)          // 1024
#define M2    162              // 2*P2
#define KE2   128              // padded K: [values(81) | 47 zeros], fp16

// ---------------- device scratch (no allocs allowed) ----------------
__device__ __align__(16) __half g_weff2h[96 * 104];   // Wefft fp16 [kout][j], pads 0
__device__ __half g_ux[CH * P2 * LL];         // Ut[c][j][l] (K-major, fp16)
__device__ __half g_uy[CH * P2 * LL];
__device__ __half g_pA[CH * LL * KE2];        // px rows fp16 [81 | 0-pad]
__device__ __half g_pB[CH * LL * KE2];

// ---------------- helpers ----------------
__device__ __forceinline__ uint32_t smem_u32(const void* p) {
    uint32_t a;
    asm("{ .reg .u64 t; cvta.to.shared.u64 t, %1; cvt.u32.u64 %0, t; }"
        : "=r"(a) : "l"(p));
    return a;
}
__device__ __forceinline__ void cpa16(uint32_t s, const void* g) {
    asm volatile("cp.async.cg.shared.global [%0], [%1], 16;" :: "r"(s), "l"(g));
}
__device__ __forceinline__ void ldmx4(uint32_t& r0, uint32_t& r1,
                                      uint32_t& r2, uint32_t& r3, uint32_t a) {
    asm volatile("ldmatrix.sync.aligned.m8n8.x4.shared.b16 {%0,%1,%2,%3}, [%4];"
                 : "=r"(r0), "=r"(r1), "=r"(r2), "=r"(r3) : "r"(a));
}
__device__ __forceinline__ void ldmx4t(uint32_t& r0, uint32_t& r1,
                                       uint32_t& r2, uint32_t& r3, uint32_t a) {
    asm volatile("ldmatrix.sync.aligned.m8n8.x4.trans.shared.b16 {%0,%1,%2,%3}, [%4];"
                 : "=r"(r0), "=r"(r1), "=r"(r2), "=r"(r3) : "r"(a));
}
__device__ __forceinline__ void mma16816(float* d, const uint32_t* a,
                                         uint32_t b0, uint32_t b1) {
    asm volatile(
        "mma.sync.aligned.m16n8k16.row.col.f32.f16.f16.f32 "
        "{%0,%1,%2,%3}, {%4,%5,%6,%7}, {%8,%9}, {%0,%1,%2,%3};"
        : "+f"(d[0]), "+f"(d[1]), "+f"(d[2]), "+f"(d[3])
        : "r"(a[0]), "r"(a[1]), "r"(a[2]), "r"(a[3]), "r"(b0), "r"(b1));
}

// ---------------- Kernel 0: Weff fp16  [kout 96][j 104], pads zero ----------
__global__ void weff_kernel(const float* __restrict__ W1,
                            const float* __restrict__ W2,
                            __half* __restrict__ We2) {
    __shared__ float w2row[M2];
    int k = blockIdx.x;     // 0..95
    int j = threadIdx.x;    // 0..103
    if (k < P2)
        for (int m = j; m < M2; m += 104) w2row[m] = W2[k * M2 + m];
    __syncthreads();
    float s = 0.f;
    if (k < P2 && j < P2) {
        #pragma unroll 6
        for (int m = 0; m < M2; m++) s += w2row[m] * W1[m * P2 + j];
    }
    We2[k * 104 + j] = __float2half_rn(s);
}

// ---------------- Kernel 1: conv + unfold -> fp16 K-major U ----------------
#define CV_THREADS 288
#define CV_SMEM ((9216 + 9216 + 1024 + 32) * 4)    // 73984 B
__global__ __launch_bounds__(CV_THREADS)
void conv_unfold(const float* __restrict__ x, const float* __restrict__ y,
                 const float* __restrict__ Wi, const float* __restrict__ bi,
                 const float* __restrict__ Wf, const float* __restrict__ bf_,
                 __half* __restrict__ ux, __half* __restrict__ uy) {
    extern __shared__ float cs[];
    float* xs = cs;            // [32][288]
    float* us = cs + 9216;     // [32][288]
    float* ws = cs + 18432;    // [32][32]
    float* bs = cs + 19456;    // [32]

    int z = blockIdx.z;
    const float* src = z ? y : x;
    const float* Wc  = z ? Wf : Wi;
    const float* bc  = z ? bf_ : bi;
    __half* U        = z ? uy : ux;

    int tid = threadIdx.x;
    int d   = blockIdx.x;              // 0..35
    int pwb = blockIdx.y;              // 0..7
    int pd = d / PP, kd = d - pd * PP;

    for (int i = tid; i < CH * CH; i += CV_THREADS) ws[i] = Wc[i];
    if (tid < CH) bs[tid] = bc[tid];

    {   // coalesced load: 32 ch x 288 floats
        const float4* x4 = (const float4*)src;
        float4* xs4 = (float4*)xs;
        int base = d * (HW / 4) + pwb * 72;
        #pragma unroll
        for (int it = 0; it < 8; it++) {
            int idx = it * CV_THREADS + tid;
            int i = idx / 72, q = idx - i * 72;
            xs4[idx] = x4[i * (DHW / 4) + base + q];
        }
    }
    __syncthreads();

    {   // conv: each thread owns one voxel
        int v = tid;
        float xv[CH];
        #pragma unroll
        for (int i = 0; i < CH; i++) xv[i] = xs[i * 288 + v];
        #pragma unroll 4
        for (int c = 0; c < CH; c++) {
            float s = bs[c];
            #pragma unroll
            for (int i = 0; i < CH; i++) s += ws[c * CH + i] * xv[i];
            us[c * 288 + v] = s;
        }
    }
    __syncthreads();

    {   // write-out fp16: rows (c,kw), 4 uint4 chunks of 8 l-values
        int l0 = pd * NW + pwb * 32;
        #pragma unroll
        for (int it = 0; it < 4; it++) {
            int idx = it * CV_THREADS + tid;       // 0..1151
            int row = idx >> 2, q = idx & 3;       // row: c*9+kw
            int c = row / PP, kw = row - c * PP;
            __half hv[8];
            #pragma unroll
            for (int t = 0; t < 8; t++)
                hv[t] = __float2half_rn(us[c * 288 + (q * 8 + t) * PP + kw]);
            *(uint4*)(U + ((size_t)(c * P2 + kd * PP + kw)) * LL + l0 + q * 8)
                = *(uint4*)hv;
        }
    }
}

// ---------------- Kernel 2: res_trans on tensor cores ----------------------
#define SU_STRIDE 272                         // bytes per sU row (17*16)
#define SW_STRIDE 208                         // bytes per sW row (13*16)
#define RT2_SMEM (96 * SU_STRIDE + 96 * SW_STRIDE)   // 46080 B
__global__ __launch_bounds__(256)
void res_trans_tc(const __half* __restrict__ U0, const __half* __restrict__ U1,
                  __half* __restrict__ P0, __half* __restrict__ P1) {
    extern __shared__ char smb[];
    uint32_t sU = smem_u32(smb);
    uint32_t sW = sU + 96 * SU_STRIDE;

    int z  = blockIdx.z;
    const __half* U = z ? U1 : U0;
    __half* Pout = z ? P1 : P0;

    int c   = blockIdx.y;
    int mb  = blockIdx.x * 128;
    int tid = threadIdx.x;
    int wid = tid >> 5, lane = tid & 31;
    int wm = wid & 1, wn = wid >> 1;          // m-slab 48 (x2), n-slab 32 (x4)

    // sU rows 0..80: straight cp.async of fp16 tile rows (16 chunks each)
    const char* Ub = (const char*)(U + (size_t)c * (P2 * LL) + mb);
    for (int idx = tid; idx < P2 * 16; idx += 256) {
        int j = idx >> 4, lc = idx & 15;
        cpa16(sU + j * SU_STRIDE + lc * 16, Ub + (size_t)j * (LL * 2) + lc * 16);
    }
    // sW: Weff fp16, 96 x 13 chunks
    {
        const char* gW = (const char*)g_weff2h;
        for (int idx = tid; idx < 96 * 13; idx += 256) {
            int row = idx / 13, ch = idx - row * 13;
            cpa16(sW + row * SW_STRIDE + ch * 16, gW + row * SW_STRIDE + ch * 16);
        }
    }
    asm volatile("cp.async.commit_group;" ::: "memory");
    // zero sU rows 81..95 (15 rows x 17 chunks) with plain stores
    {
        uint4 zero4 = make_uint4(0, 0, 0, 0);
        for (int idx = tid; idx < 15 * 17; idx += 256) {
            int j = P2 + idx / 17, ch = idx % 17;
            *(uint4*)(smb + j * SU_STRIDE + ch * 16) = zero4;
        }
    }
    asm volatile("cp.async.wait_group 0;" ::: "memory");
    __syncthreads();

    float acc[3][4][4];
    #pragma unroll
    for (int i = 0; i < 3; i++)
        #pragma unroll
        for (int j = 0; j < 4; j++)
            #pragma unroll
            for (int q = 0; q < 4; q++) acc[i][j][q] = 0.f;

    int tr = lane & 15, tc = lane >> 4;

    #pragma unroll
    for (int ks = 0; ks < 6; ks++) {
        int j0 = ks * 16;
        uint32_t afr[3][4];
        #pragma unroll
        for (int i = 0; i < 3; i++) {
            int m0 = wm * 48 + i * 16;
            ldmx4(afr[i][0], afr[i][1], afr[i][2], afr[i][3],
                  sW + (m0 + tr) * SW_STRIDE + j0 * 2 + tc * 16);
        }
        uint32_t b0[4], b1[4];
        #pragma unroll
        for (int jj = 0; jj < 2; jj++) {
            int n0 = wn * 32 + jj * 16;
            uint32_t r0, r1, r2, r3;
            ldmx4t(r0, r1, r2, r3,
                   sU + (j0 + tr) * SU_STRIDE + (n0 + tc * 8) * 2);
            b0[jj*2]   = r0; b1[jj*2]   = r1;
            b0[jj*2+1] = r2; b1[jj*2+1] = r3;
        }
        #pragma unroll
        for (int i = 0; i < 3; i++)
            #pragma unroll
            for (int j = 0; j < 4; j++)
                mma16816(acc[i][j], afr[i], b0[j], b1[j]);
    }
    __syncthreads();

    __half* st = (__half*)smb;
    int r0 = lane >> 2, c0 = (lane & 3) * 2;
    #pragma unroll
    for (int i = 0; i < 3; i++) {
        #pragma unroll
        for (int j = 0; j < 4; j++) {
            int m0 = wm * 48 + i * 16 + r0;
            int n0 = wn * 32 + j * 8 + c0;
            #pragma unroll
            for (int q = 0; q < 4; q++) {
                float v = acc[i][j][q];
                v = (v > 0.f) ? v : 0.2f * v;
                int mm = m0 + (q >> 1) * 8;
                int nn = n0 + (q & 1);
                st[nn * 104 + mm] = __float2half_rn(v);
            }
        }
    }
    __syncthreads();

    uint4* g4 = (uint4*)(Pout + ((size_t)(c * LL + mb)) * KE2);
    const char* stb = smb;
    uint4 zero4 = make_uint4(0, 0, 0, 0);
    #pragma unroll
    for (int it = 0; it < 8; it++) {
        int idx = it * 256 + tid;            // 0..2047
        int r = idx >> 4, q = idx & 15;
        uint4 v = (q < 12) ? *(const uint4*)(stb + r * SW_STRIDE + q * 16) : zero4;
        g4[r * 16 + q] = v;
    }
}

// ---------------- Kernel 3: att GEMM, 128x256 CTA tile, sequential halves --
// A loaded once; B0/B1 in separate cp.async groups. 8 warps, warp tile 64x32
// (the proven LDSM/MMA ratio). Store of half 0 overlaps compute of half 1.
#define AT_SMEM 98304          // A 32KB + B0 32KB + B1 32KB
__global__ __launch_bounds__(256, 2)
void att_mma(const __half* __restrict__ pA,
             const __half* __restrict__ pB,
             float* __restrict__ att) {
    extern __shared__ char smb[];
    uint32_t sA  = smem_u32(smb);
    uint32_t sB0 = sA + 32768;
    uint32_t sB1 = sB0 + 32768;

    int tid  = threadIdx.x;
    int wid  = tid >> 5;
    int lane = tid & 31;
    int wm   = wid & 1;        // 2 m-slabs (64 rows)
    int wn   = wid >> 1;       // 4 n-slabs (32 cols)

    int c  = blockIdx.z;
    int mb = blockIdx.y * 128;
    int nb = blockIdx.x * 256;
    const char* Ab = (const char*)(pA + ((size_t)(c * LL + mb)) * KE2);
    const char* Bb = (const char*)(pB + ((size_t)(c * LL + nb)) * KE2);

    // group 1: A + B0 (128 rows x 256 B each)
    #pragma unroll
    for (int it = 0; it < 8; it++) {
        int idx = it * 256 + tid;
        int row = idx >> 4, ch = idx & 15;
        int chs = ch ^ (row & 7);
        cpa16(sA  + row * 256 + chs * 16, Ab + row * 256 + ch * 16);
        cpa16(sB0 + row * 256 + chs * 16, Bb + row * 256 + ch * 16);
    }
    asm volatile("cp.async.commit_group;" ::: "memory");
    // group 2: B1 (rows 128..255 of the B slab)
    #pragma unroll
    for (int it = 0; it < 8; it++) {
        int idx = it * 256 + tid;
        int row = idx >> 4, ch = idx & 15;
        int chs = ch ^ (row & 7);
        cpa16(sB1 + row * 256 + chs * 16, Bb + 32768 + row * 256 + ch * 16);
    }
    asm volatile("cp.async.commit_group;" ::: "memory");

    int tr   = lane & 15;
    int tc   = lane >> 4;
    int xorv = tr & 7;
    uint32_t aRow = sA + (wm * 64 + tr) * 256;
    const float scale = 1.0f / 81.0f;
    int r0 = lane >> 2;
    int c0 = (lane & 3) * 2;

    #pragma unroll
    for (int h = 0; h < 2; h++) {
        if (h == 0) asm volatile("cp.async.wait_group 1;" ::: "memory");
        else        asm volatile("cp.async.wait_group 0;" ::: "memory");
        __syncthreads();

        float acc[4][4][4];
        #pragma unroll
        for (int i = 0; i < 4; i++)
            #pragma unroll
            for (int j = 0; j < 4; j++)
                #pragma unroll
                for (int q = 0; q < 4; q++) acc[i][j][q] = 0.f;

        uint32_t bRow = (h ? sB1 : sB0) + (wn * 32 + tr) * 256;

        #pragma unroll
        for (int k = 0; k < 8; k++) {
            uint32_t chs = (uint32_t)(((2 * k + tc) ^ xorv) << 4);
            uint32_t afr[4][4];
            #pragma unroll
            for (int i = 0; i < 4; i++)
                ldmx4(afr[i][0], afr[i][1], afr[i][2], afr[i][3],
                      aRow + i * 4096 + chs);
            uint32_t b0[4], b1[4];
            #pragma unroll
            for (int j = 0; j < 2; j++) {
                uint32_t r0x, r1x, r2x, r3x;
                ldmx4(r0x, r1x, r2x, r3x, bRow + j * 4096 + chs);
                b0[j*2]   = r0x; b1[j*2]   = r2x;
                b0[j*2+1] = r1x; b1[j*2+1] = r3x;
            }
            #pragma unroll
            for (int i = 0; i < 4; i++)
                #pragma unroll
                for (int j = 0; j < 4; j++)
                    mma16816(acc[i][j], afr[i], b0[j], b1[j]);
        }

        // epilogue for this half (STGs overlap next half's compute)
        #pragma unroll
        for (int i = 0; i < 4; i++) {
            #pragma unroll
            for (int j = 0; j < 4; j++) {
                size_t row = (size_t)(mb + wm * 64 + i * 16 + r0);
                float* o = att + (size_t)c * LL * LL + row * LL
                         + nb + h * 128 + wn * 32 + j * 8 + c0;
                *(float2*)o            = make_float2(acc[i][j][0] * scale,
                                                     acc[i][j][1] * scale);
                *(float2*)(o + 8 * LL) = make_float2(acc[i][j][2] * scale,
                                                     acc[i][j][3] * scale);
            }
        }
    }
}

// ---------------- launch ----------------
extern "C" void kernel_launch(void* const* d_in, const int* in_sizes, int n_in,
                              void* d_out, int out_size) {
    const float* x     = (const float*)d_in[0];
    const float* y     = (const float*)d_in[1];
    const float* W_img = (const float*)d_in[2];
    const float* b_img = (const float*)d_in[3];
    const float* W_fea = (const float*)d_in[4];
    const float* b_fea = (const float*)d_in[5];
    const float* W1    = (const float*)d_in[6];
    const float* W2    = (const float*)d_in[7];
    float* out = (float*)d_out;

    __half *we2, *ux, *uy, *pA, *pB;
    cudaGetSymbolAddress((void**)&we2, g_weff2h);
    cudaGetSymbolAddress((void**)&ux,  g_ux);
    cudaGetSymbolAddress((void**)&uy,  g_uy);
    cudaGetSymbolAddress((void**)&pA,  g_pA);
    cudaGetSymbolAddress((void**)&pB,  g_pB);

    static bool attr_set = false;
    if (!attr_set) {
        cudaFuncSetAttribute(att_mma, cudaFuncAttributeMaxDynamicSharedMemorySize,
                             AT_SMEM);
        cudaFuncSetAttribute(res_trans_tc,
                             cudaFuncAttributeMaxDynamicSharedMemorySize, RT2_SMEM);
        cudaFuncSetAttribute(conv_unfold,
                             cudaFuncAttributeMaxDynamicSharedMemorySize, CV_SMEM);
        attr_set = true;
    }

    weff_kernel<<<96, 104>>>(W1, W2, we2);
    {
        dim3 g(DD, 8, 2);
        conv_unfold<<<g, CV_THREADS, CV_SMEM>>>(x, y, W_img, b_img,
                                                W_fea, b_fea, ux, uy);
    }
    {
        dim3 g(LL / 128, CH, 2);          // (8, 32, 2)
        res_trans_tc<<<g, 256, RT2_SMEM>>>(ux, uy, pA, pB);
    }
    {
        dim3 g(LL / 256, LL / 128, CH);   // (4, 8, 32)
        att_mma<<<g, 256, AT_SMEM>>>(pA, pB, out);
    }
}